// round 1
// baseline (speedup 1.0000x reference)
#include <cuda_runtime.h>
#include <cuda_bf16.h>
#include <math.h>

// ---------------- problem constants ----------------
#define BB 8
#define NN 1024
#define CC 512
#define NHD 8
#define DH 64
#define FF 2048
#define M_TOK (BB*NN)          // 8192
#define HEADS (BB*NHD)         // 64
#define SCALE 0.125f           // 64^-0.5

// ---------------- scratch (static device, no allocs) ----------------
__device__ float g_xn[M_TOK*CC];            // ln1 output
__device__ float g_qkv[M_TOK*3*CC];         // qkv
__device__ float g_qbar[HEADS*DH];
__device__ float g_kbar[HEADS*DH];
__device__ float g_scores[2*HEADS*NN];      // row scores then col scores
__device__ float g_mask[2*HEADS*NN];        // row masks then col masks
__device__ float g_S[(size_t)HEADS*NN*NN];  // 256 MB attention scores / probs
__device__ float g_attn[M_TOK*CC];          // attention output (pre-proj)
__device__ float g_conv[M_TOK*CC];          // conv branch
__device__ float g_xr[M_TOK*CC];            // x_attn + x_conv
__device__ float g_h[M_TOK*CC];             // ln2 output
__device__ float g_ff[M_TOK*FF];            // ff1 output

// ---------------- layernorm ----------------
__global__ void ln_kernel(const float* __restrict__ x, const float* __restrict__ w,
                          const float* __restrict__ b, float* __restrict__ y) {
    int row = blockIdx.x;
    int tid = threadIdx.x;               // 256 threads, 2 elems each
    const float* xr = x + (size_t)row*CC;
    float v0 = xr[tid], v1 = xr[tid+256];
    __shared__ float red[256];
    red[tid] = v0 + v1; __syncthreads();
    for (int s = 128; s > 0; s >>= 1) { if (tid < s) red[tid] += red[tid+s]; __syncthreads(); }
    float mu = red[0] * (1.0f/CC);
    __syncthreads();
    float d0 = v0 - mu, d1 = v1 - mu;
    red[tid] = d0*d0 + d1*d1; __syncthreads();
    for (int s = 128; s > 0; s >>= 1) { if (tid < s) red[tid] += red[tid+s]; __syncthreads(); }
    float rs = rsqrtf(red[0] * (1.0f/CC) + 1e-6f);
    float* yr = y + (size_t)row*CC;
    yr[tid]     = d0*rs*w[tid]     + b[tid];
    yr[tid+256] = d1*rs*w[tid+256] + b[tid+256];
}

// ---------------- generic NT SGEMM: C[M,N] = A[M,K] * B[N,K]^T ----------------
// EP: 0 = plain, 1 = +bias[n] (+addm[m,n] if addm), 2 = gelu(v + bias[n])
template<int EP>
__global__ void sgemm_nt(const float* __restrict__ A, const float* __restrict__ B,
                         float* __restrict__ C, int M, int N, int K,
                         const float* __restrict__ bias, const float* __restrict__ addm) {
    const int bm = blockIdx.y * 128, bn = blockIdx.x * 128;
    __shared__ float As[8][128];
    __shared__ float Bs[8][128];
    int tid = threadIdx.x;
    int ty = tid >> 4, tx = tid & 15;
    int lrow = tid >> 1, lk4 = (tid & 1) * 4;
    float acc[8][8];
    #pragma unroll
    for (int i = 0; i < 8; i++)
        #pragma unroll
        for (int j = 0; j < 8; j++) acc[i][j] = 0.f;

    const float* Ab = A + (size_t)(bm + lrow) * K + lk4;
    const float* Bb = B + (size_t)(bn + lrow) * K + lk4;

    for (int kt = 0; kt < K; kt += 8) {
        float4 av = *(const float4*)(Ab + kt);
        float4 bv = *(const float4*)(Bb + kt);
        As[lk4+0][lrow] = av.x; As[lk4+1][lrow] = av.y;
        As[lk4+2][lrow] = av.z; As[lk4+3][lrow] = av.w;
        Bs[lk4+0][lrow] = bv.x; Bs[lk4+1][lrow] = bv.y;
        Bs[lk4+2][lrow] = bv.z; Bs[lk4+3][lrow] = bv.w;
        __syncthreads();
        #pragma unroll
        for (int k = 0; k < 8; k++) {
            float a[8], bb[8];
            *(float4*)(a)   = *(const float4*)&As[k][ty*8];
            *(float4*)(a+4) = *(const float4*)&As[k][ty*8+4];
            *(float4*)(bb)   = *(const float4*)&Bs[k][tx*8];
            *(float4*)(bb+4) = *(const float4*)&Bs[k][tx*8+4];
            #pragma unroll
            for (int i = 0; i < 8; i++)
                #pragma unroll
                for (int j = 0; j < 8; j++) acc[i][j] += a[i]*bb[j];
        }
        __syncthreads();
    }

    #pragma unroll
    for (int i = 0; i < 8; i++) {
        int row = bm + ty*8 + i;
        size_t off = (size_t)row * N + bn + tx*8;
        #pragma unroll
        for (int j = 0; j < 8; j++) {
            float v = acc[i][j];
            if (EP >= 1) v += bias[bn + tx*8 + j];
            if (EP == 1 && addm) v += addm[off + j];
            if (EP == 2) v = 0.5f * v * (1.0f + erff(v * 0.70710678118654752f));
            C[off + j] = v;
        }
    }
}

// ---------------- per-head mean of q and k ----------------
__global__ void head_means(const float* __restrict__ qkv, float* __restrict__ qbar,
                           float* __restrict__ kbar) {
    int bh = blockIdx.x, b = bh >> 3, h = bh & 7;
    int tid = threadIdx.x;
    int d = tid & 63, part = tid >> 6;       // 4 parts of 256 rows
    const float* base = qkv + (size_t)b*NN*(3*CC) + h*DH + d;
    float sq = 0.f, sk = 0.f;
    for (int r = part*256; r < part*256 + 256; ++r) {
        const float* p = base + (size_t)r*(3*CC);
        sq += p[0]; sk += p[CC];
    }
    __shared__ float shq[256], shk[256];
    shq[tid] = sq; shk[tid] = sk; __syncthreads();
    if (part == 0) {
        float a = shq[tid] + shq[tid+64] + shq[tid+128] + shq[tid+192];
        float c = shk[tid] + shk[tid+64] + shk[tid+128] + shk[tid+192];
        qbar[bh*DH + d] = a * (1.0f/NN);
        kbar[bh*DH + d] = c * (1.0f/NN);
    }
}

// ---------------- row/col scores: scale * q_i . kbar,  scale * qbar . k_j ----------------
__global__ void head_scores(const float* __restrict__ qkv, const float* __restrict__ qbar,
                            const float* __restrict__ kbar, float* __restrict__ scores) {
    int bh = blockIdx.y, b = bh >> 3, h = bh & 7;
    int i = blockIdx.x * blockDim.x + threadIdx.x;  // 0..1023
    const float* row = qkv + (size_t)(b*NN + i)*(3*CC) + h*DH;
    float rs = 0.f, cs = 0.f;
    #pragma unroll
    for (int d = 0; d < DH; d++) {
        rs += row[d]      * kbar[bh*DH + d];
        cs += qbar[bh*DH + d] * row[CC + d];
    }
    scores[bh*NN + i]              = rs * SCALE;
    scores[HEADS*NN + bh*NN + i]   = cs * SCALE;
}

// ---------------- top-k threshold (k=512 of 1024) + mask, bitonic sort ----------------
__global__ void topk_mask(const float* __restrict__ scores, float* __restrict__ mask) {
    __shared__ float s[1024];
    int blk = blockIdx.x, tid = threadIdx.x;
    float v = scores[(size_t)blk*1024 + tid];
    s[tid] = v; __syncthreads();
    for (int k = 2; k <= 1024; k <<= 1) {
        for (int j = k >> 1; j > 0; j >>= 1) {
            int ixj = tid ^ j;
            if (ixj > tid) {
                bool up = ((tid & k) == 0);
                float a = s[tid], bb = s[ixj];
                if ((a > bb) == up) { s[tid] = bb; s[ixj] = a; }
            }
            __syncthreads();
        }
    }
    float thr = s[512];   // 512th largest (ascending sort)
    mask[(size_t)blk*1024 + tid] = (v >= thr) ? 1.0f : 0.0f;
}

// ---------------- masked attention scores: S = (q k^T)*scale * rm_i * cm_j ----------------
__global__ void attn_score(const float* __restrict__ qkv, const float* __restrict__ mask,
                           float* __restrict__ S) {
    int bh = blockIdx.z, b = bh >> 3, h = bh & 7;
    int bm = blockIdx.y * 64, bn = blockIdx.x * 64;
    __shared__ float Qs[64][66];   // [k][m]
    __shared__ float Ks[64][66];   // [k][n]
    int tid = threadIdx.x;
    const float* qbase = qkv + (size_t)b*NN*(3*CC) + h*DH;
    for (int idx = tid; idx < 4096; idx += 256) {
        int r = idx >> 6, c = idx & 63;
        Qs[c][r] = qbase[(size_t)(bm + r)*(3*CC) + c];
        Ks[c][r] = qbase[(size_t)(bn + r)*(3*CC) + CC + c];
    }
    __syncthreads();
    int ty = tid >> 4, tx = tid & 15;
    float acc[4][4] = {};
    #pragma unroll
    for (int k = 0; k < 64; k++) {
        float a[4], bb[4];
        #pragma unroll
        for (int i = 0; i < 4; i++) a[i]  = Qs[k][ty*4 + i];
        #pragma unroll
        for (int j = 0; j < 4; j++) bb[j] = Ks[k][tx*4 + j];
        #pragma unroll
        for (int i = 0; i < 4; i++)
            #pragma unroll
            for (int j = 0; j < 4; j++) acc[i][j] += a[i]*bb[j];
    }
    #pragma unroll
    for (int i = 0; i < 4; i++) {
        int row = bm + ty*4 + i;
        float rm = mask[bh*NN + row];
        #pragma unroll
        for (int j = 0; j < 4; j++) {
            int col = bn + tx*4 + j;
            float cm = mask[HEADS*NN + bh*NN + col];
            S[((size_t)bh << 20) + (size_t)row*NN + col] = acc[i][j] * SCALE * rm * cm;
        }
    }
}

// ---------------- softmax over rows of 1024 (in place) ----------------
__global__ void softmax_rows(float* __restrict__ S) {
    size_t row = blockIdx.x;
    float* p = S + row * NN;
    int tid = threadIdx.x;
    float v[4];
    float mx = -1e30f;
    #pragma unroll
    for (int j = 0; j < 4; j++) { v[j] = p[tid + j*256]; mx = fmaxf(mx, v[j]); }
    __shared__ float red[256];
    red[tid] = mx; __syncthreads();
    for (int s = 128; s > 0; s >>= 1) { if (tid < s) red[tid] = fmaxf(red[tid], red[tid+s]); __syncthreads(); }
    mx = red[0]; __syncthreads();
    float sum = 0.f;
    #pragma unroll
    for (int j = 0; j < 4; j++) { v[j] = __expf(v[j] - mx); sum += v[j]; }
    red[tid] = sum; __syncthreads();
    for (int s = 128; s > 0; s >>= 1) { if (tid < s) red[tid] += red[tid+s]; __syncthreads(); }
    float inv = 1.0f / red[0];
    #pragma unroll
    for (int j = 0; j < 4; j++) p[tid + j*256] = v[j] * inv;
}

// ---------------- P @ V per head ----------------
__global__ void attn_pv(const float* __restrict__ S, const float* __restrict__ qkv,
                        float* __restrict__ out) {
    int bh = blockIdx.z, b = bh >> 3, h = bh & 7;
    int bm = blockIdx.x * 64;
    __shared__ float Ps[32][66];   // [k][m]
    __shared__ float Vs[32][64];   // [k][c]
    const float* Pbase = S + ((size_t)bh << 20);
    const float* vbase = qkv + (size_t)b*NN*(3*CC) + 2*CC + h*DH;
    int tid = threadIdx.x;
    int ty = tid >> 4, tx = tid & 15;
    float acc[4][4] = {};
    for (int kt = 0; kt < NN; kt += 32) {
        for (int idx = tid; idx < 2048; idx += 256) {
            int m = idx >> 5, k = idx & 31;
            Ps[k][m] = Pbase[(size_t)(bm + m)*NN + kt + k];
        }
        for (int idx = tid; idx < 2048; idx += 256) {
            int k = idx >> 6, c = idx & 63;
            Vs[k][c] = vbase[(size_t)(kt + k)*(3*CC) + c];
        }
        __syncthreads();
        #pragma unroll
        for (int k = 0; k < 32; k++) {
            float a[4], bb[4];
            #pragma unroll
            for (int i = 0; i < 4; i++) a[i]  = Ps[k][ty*4 + i];
            #pragma unroll
            for (int j = 0; j < 4; j++) bb[j] = Vs[k][tx*4 + j];
            #pragma unroll
            for (int i = 0; i < 4; i++)
                #pragma unroll
                for (int j = 0; j < 4; j++) acc[i][j] += a[i]*bb[j];
        }
        __syncthreads();
    }
    #pragma unroll
    for (int i = 0; i < 4; i++) {
        int tok = b*NN + bm + ty*4 + i;
        #pragma unroll
        for (int j = 0; j < 4; j++)
            out[(size_t)tok*CC + h*DH + tx*4 + j] = acc[i][j];
    }
}

// ---------------- depthwise 3x3 conv branch ----------------
__global__ void dwconv(const float* __restrict__ x, const float* __restrict__ w,
                       const float* __restrict__ b, float* __restrict__ out) {
    int bn = blockIdx.x;            // b*1024 + n
    int bt = bn >> 10, n = bn & 1023;
    int hh = n >> 5, ww = n & 31;
    int c = threadIdx.x;            // 512 threads
    float acc = b[c];
    #pragma unroll
    for (int dh = 0; dh < 3; dh++) {
        int y = hh + dh - 1;
        if (y < 0 || y >= 32) continue;
        #pragma unroll
        for (int dw = 0; dw < 3; dw++) {
            int xw = ww + dw - 1;
            if (xw < 0 || xw >= 32) continue;
            acc += x[(size_t)(bt*NN + y*32 + xw)*CC + c] * w[c*9 + dh*3 + dw];
        }
    }
    out[(size_t)bn*CC + c] = acc;
}

// ---------------- launch ----------------
extern "C" void kernel_launch(void* const* d_in, const int* in_sizes, int n_in,
                              void* d_out, int out_size) {
    const float* x      = (const float*)d_in[0];
    const float* ln1_w  = (const float*)d_in[1];
    const float* ln1_b  = (const float*)d_in[2];
    const float* qkv_w  = (const float*)d_in[3];
    const float* out_w  = (const float*)d_in[4];
    const float* out_b  = (const float*)d_in[5];
    const float* conv_w = (const float*)d_in[6];
    const float* conv_b = (const float*)d_in[7];
    const float* ln2_w  = (const float*)d_in[8];
    const float* ln2_b  = (const float*)d_in[9];
    const float* ff1_w  = (const float*)d_in[10];
    const float* ff1_b  = (const float*)d_in[11];
    const float* ff2_w  = (const float*)d_in[12];
    const float* ff2_b  = (const float*)d_in[13];
    float* out = (float*)d_out;

    float *xn, *qkv, *qbar, *kbar, *scores, *mask, *S, *attn, *conv, *xr, *hbuf, *ff;
    cudaGetSymbolAddress((void**)&xn,     g_xn);
    cudaGetSymbolAddress((void**)&qkv,    g_qkv);
    cudaGetSymbolAddress((void**)&qbar,   g_qbar);
    cudaGetSymbolAddress((void**)&kbar,   g_kbar);
    cudaGetSymbolAddress((void**)&scores, g_scores);
    cudaGetSymbolAddress((void**)&mask,   g_mask);
    cudaGetSymbolAddress((void**)&S,      g_S);
    cudaGetSymbolAddress((void**)&attn,   g_attn);
    cudaGetSymbolAddress((void**)&conv,   g_conv);
    cudaGetSymbolAddress((void**)&xr,     g_xr);
    cudaGetSymbolAddress((void**)&hbuf,   g_h);
    cudaGetSymbolAddress((void**)&ff,     g_ff);

    // 1. LN1
    ln_kernel<<<M_TOK, 256>>>(x, ln1_w, ln1_b, xn);
    // 2. QKV = xn @ qkv_w^T
    sgemm_nt<0><<<dim3(3*CC/128, M_TOK/128), 256>>>(xn, qkv_w, qkv, M_TOK, 3*CC, CC, nullptr, nullptr);
    // 3. per-head means, 4. scores, 5. thresholds + masks
    head_means<<<HEADS, 256>>>(qkv, qbar, kbar);
    head_scores<<<dim3(4, HEADS), 256>>>(qkv, qbar, kbar, scores);
    topk_mask<<<2*HEADS, 1024>>>(scores, mask);
    // 6. masked scores
    attn_score<<<dim3(16, 16, HEADS), 256>>>(qkv, mask, S);
    // 7. softmax
    softmax_rows<<<HEADS*NN, 256>>>(S);
    // 8. P @ V
    attn_pv<<<dim3(16, 1, HEADS), 256>>>(S, qkv, attn);
    // 9. conv branch
    dwconv<<<M_TOK, CC>>>(x, conv_w, conv_b, conv);
    // 10. out-proj + out_b + conv  -> xr
    sgemm_nt<1><<<dim3(CC/128, M_TOK/128), 256>>>(attn, out_w, xr, M_TOK, CC, CC, out_b, conv);
    // 11. LN2
    ln_kernel<<<M_TOK, 256>>>(xr, ln2_w, ln2_b, hbuf);
    // 12. FF1 + gelu
    sgemm_nt<2><<<dim3(FF/128, M_TOK/128), 256>>>(hbuf, ff1_w, ff, M_TOK, FF, CC, ff1_b, nullptr);
    // 13. FF2 + ff2_b + residual xr -> out
    sgemm_nt<1><<<dim3(CC/128, M_TOK/128), 256>>>(ff, ff2_w, out, M_TOK, CC, FF, ff2_b, xr);
}

// round 2
// speedup vs baseline: 1.9952x; 1.9952x over previous
#include <cuda_runtime.h>
#include <math.h>
#include <stdint.h>

// ---------------- problem constants ----------------
#define BB 8
#define NN 1024
#define CC 512
#define FF 2048
#define M_TOK (BB*NN)          // 8192
#define HEADS 64
#define SCALE 0.125f           // 64^-0.5

// ---------------- scratch (static device, no allocs) ----------------
__device__ float g_xn[M_TOK*CC];            // ln1 output
__device__ float g_qkv[M_TOK*3*CC];         // qkv
__device__ float g_part[64*CC];             // xn partial sums [b][p][c]
__device__ float g_w[2*HEADS*CC];           // wrow then wcol
__device__ float g_scores[2*HEADS*NN];      // row scores then col scores
__device__ float g_mask[2*HEADS*NN];        // row masks then col masks
__device__ float g_S[(size_t)HEADS*NN*NN];  // 256 MB attention scores / probs
__device__ float g_attn[M_TOK*CC];          // attention output (pre-proj)
__device__ float g_conv[M_TOK*CC];          // conv branch
__device__ float g_xr[M_TOK*CC];            // x_attn + x_conv
__device__ float g_h[M_TOK*CC];             // ln2 output
__device__ float g_ff[M_TOK*FF];            // ff1 output

// ---------------- layernorm ----------------
__global__ void ln_kernel(const float* __restrict__ x, const float* __restrict__ w,
                          const float* __restrict__ b, float* __restrict__ y) {
    int row = blockIdx.x;
    int tid = threadIdx.x;               // 256 threads, 2 elems each
    const float* xr = x + (size_t)row*CC;
    float v0 = xr[tid], v1 = xr[tid+256];
    __shared__ float red[256];
    red[tid] = v0 + v1; __syncthreads();
    for (int s = 128; s > 0; s >>= 1) { if (tid < s) red[tid] += red[tid+s]; __syncthreads(); }
    float mu = red[0] * (1.0f/CC);
    __syncthreads();
    float d0 = v0 - mu, d1 = v1 - mu;
    red[tid] = d0*d0 + d1*d1; __syncthreads();
    for (int s = 128; s > 0; s >>= 1) { if (tid < s) red[tid] += red[tid+s]; __syncthreads(); }
    float rs = rsqrtf(red[0] * (1.0f/CC) + 1e-6f);
    float* yr = y + (size_t)row*CC;
    yr[tid]     = d0*rs*w[tid]     + b[tid];
    yr[tid+256] = d1*rs*w[tid+256] + b[tid+256];
}

// ---------------- xn partial sums for per-batch mean ----------------
__global__ void xn_part(const float* __restrict__ xn, float* __restrict__ part) {
    int b = blockIdx.x, p = blockIdx.y;
    int c = threadIdx.x;    // 512
    const float* base = xn + ((size_t)b*NN + p*128)*CC + c;
    float s = 0.f;
    #pragma unroll 8
    for (int r = 0; r < 128; r++) s += base[(size_t)r*CC];
    part[(b*8+p)*CC + c] = s;
}

// ---------------- exact-fp32 mask projection vectors ----------------
// wrow_bh = Wq_h^T (Wk_h xbar_b), wcol_bh = Wk_h^T (Wq_h xbar_b)
__global__ void wvec(const float* __restrict__ part, const float* __restrict__ qkv_w,
                     float* __restrict__ w) {
    int bh = blockIdx.x, b = bh >> 3, h = bh & 7;
    int t = threadIdx.x;    // 512
    __shared__ float xb[512];
    __shared__ float kb[64], qb[64];
    float s = 0.f;
    #pragma unroll
    for (int p = 0; p < 8; p++) s += part[(b*8+p)*CC + t];
    xb[t] = s * (1.0f/NN);
    __syncthreads();
    if (t < 64) {
        float sq = 0.f, sk = 0.f;
        const float* wq = qkv_w + (size_t)(h*64 + t)*CC;
        const float* wk = qkv_w + (size_t)(CC + h*64 + t)*CC;
        for (int c = 0; c < CC; c++) { sq += wq[c]*xb[c]; sk += wk[c]*xb[c]; }
        qb[t] = sq; kb[t] = sk;
    }
    __syncthreads();
    float wr = 0.f, wc = 0.f;
    #pragma unroll 8
    for (int d = 0; d < 64; d++) {
        wr += qkv_w[(size_t)(h*64+d)*CC + t]    * kb[d];
        wc += qkv_w[(size_t)(CC+h*64+d)*CC + t] * qb[d];
    }
    w[bh*CC + t]            = wr;
    w[HEADS*CC + bh*CC + t] = wc;
}

// ---------------- row/col scores: exact fp32 dot xn . w ----------------
__global__ void head_scores2(const float* __restrict__ xn, const float* __restrict__ w,
                             float* __restrict__ scores) {
    int bh = blockIdx.x, b = bh >> 3;
    int tok0 = blockIdx.y * 8;
    __shared__ float wr[512], wc[512];
    int tid = threadIdx.x;   // 256
    wr[tid]     = w[bh*CC + tid];
    wr[tid+256] = w[bh*CC + tid + 256];
    wc[tid]     = w[HEADS*CC + bh*CC + tid];
    wc[tid+256] = w[HEADS*CC + bh*CC + tid + 256];
    __syncthreads();
    int wp = tid >> 5, lane = tid & 31;
    int i = tok0 + wp;
    const float* xr = xn + (size_t)(b*NN + i)*CC;
    float sr = 0.f, sc = 0.f;
    #pragma unroll
    for (int c = lane; c < CC; c += 32) { float v = xr[c]; sr += v*wr[c]; sc += v*wc[c]; }
    #pragma unroll
    for (int o = 16; o > 0; o >>= 1) {
        sr += __shfl_down_sync(~0u, sr, o);
        sc += __shfl_down_sync(~0u, sc, o);
    }
    if (lane == 0) {
        scores[bh*NN + i]            = sr * SCALE;
        scores[HEADS*NN + bh*NN + i] = sc * SCALE;
    }
}

// ---------------- top-k threshold (k=512 of 1024) + mask, bitonic sort ----------------
__global__ void topk_mask(const float* __restrict__ scores, float* __restrict__ mask) {
    __shared__ float s[1024];
    int blk = blockIdx.x, tid = threadIdx.x;
    float v = scores[(size_t)blk*1024 + tid];
    s[tid] = v; __syncthreads();
    for (int k = 2; k <= 1024; k <<= 1) {
        for (int j = k >> 1; j > 0; j >>= 1) {
            int ixj = tid ^ j;
            if (ixj > tid) {
                bool up = ((tid & k) == 0);
                float a = s[tid], bb = s[ixj];
                if ((a > bb) == up) { s[tid] = bb; s[ixj] = a; }
            }
            __syncthreads();
        }
    }
    float thr = s[512];
    mask[(size_t)blk*1024 + tid] = (v >= thr) ? 1.0f : 0.0f;
}

// ---------------- softmax over rows of 1024 (in place) ----------------
__global__ void softmax_rows(float* __restrict__ S) {
    size_t row = blockIdx.x;
    float* p = S + row * NN;
    int tid = threadIdx.x;
    float v[4];
    float mx = -1e30f;
    #pragma unroll
    for (int j = 0; j < 4; j++) { v[j] = p[tid + j*256]; mx = fmaxf(mx, v[j]); }
    __shared__ float red[256];
    red[tid] = mx; __syncthreads();
    for (int s = 128; s > 0; s >>= 1) { if (tid < s) red[tid] = fmaxf(red[tid], red[tid+s]); __syncthreads(); }
    mx = red[0]; __syncthreads();
    float sum = 0.f;
    #pragma unroll
    for (int j = 0; j < 4; j++) { v[j] = __expf(v[j] - mx); sum += v[j]; }
    red[tid] = sum; __syncthreads();
    for (int s = 128; s > 0; s >>= 1) { if (tid < s) red[tid] += red[tid+s]; __syncthreads(); }
    float inv = 1.0f / red[0];
    #pragma unroll
    for (int j = 0; j < 4; j++) p[tid + j*256] = v[j] * inv;
}

// ---------------- depthwise 3x3 conv branch ----------------
__global__ void dwconv(const float* __restrict__ x, const float* __restrict__ w,
                       const float* __restrict__ b, float* __restrict__ out) {
    int bn = blockIdx.x;
    int bt = bn >> 10, n = bn & 1023;
    int hh = n >> 5, ww = n & 31;
    int c = threadIdx.x;            // 512 threads
    float acc = b[c];
    #pragma unroll
    for (int dh = 0; dh < 3; dh++) {
        int y = hh + dh - 1;
        if (y < 0 || y >= 32) continue;
        #pragma unroll
        for (int dw = 0; dw < 3; dw++) {
            int xw = ww + dw - 1;
            if (xw < 0 || xw >= 32) continue;
            acc += x[(size_t)(bt*NN + y*32 + xw)*CC + c] * w[c*9 + dh*3 + dw];
        }
    }
    out[(size_t)bn*CC + c] = acc;
}

// ---------------- tf32 tensor-core GEMM ----------------
__device__ __forceinline__ uint32_t f2tf(float x) {
    uint32_t u;
    asm("cvt.rna.tf32.f32 %0, %1;" : "=r"(u) : "f"(x));
    return u;
}

__device__ __forceinline__ void mma8(float* c, const uint32_t* a, const uint32_t* b) {
    asm volatile("mma.sync.aligned.m16n8k8.row.col.f32.tf32.tf32.f32 "
                 "{%0,%1,%2,%3},{%4,%5,%6,%7},{%8,%9},{%0,%1,%2,%3};\n"
                 : "+f"(c[0]), "+f"(c[1]), "+f"(c[2]), "+f"(c[3])
                 : "r"(a[0]), "r"(a[1]), "r"(a[2]), "r"(a[3]), "r"(b[0]), "r"(b[1]));
}

// C[M,N] = A[M,K] @ op(B) where op(B) = B^T if BT (B is [N,K] row-major),
// else B is [K,N] row-major. Batched via blockIdx.z: ptr += (z>>3)*Hi + (z&7)*Lo.
// EP: 0 plain; 1 +bias[n] (+addm same-layout); 2 gelu(v+bias[n]); 3 v*SCALE*rm*cm.
template<int BN, int EP, bool BT>
__global__ __launch_bounds__(256)
void tgemm(const float* __restrict__ A, int lda, long long aHi, long long aLo,
           const float* __restrict__ B, int ldb, long long bHi, long long bLo,
           float* __restrict__ C, int ldc, long long cHi, long long cLo,
           int K,
           const float* __restrict__ bias, const float* __restrict__ addm,
           const float* __restrict__ mask)
{
    constexpr int BM = 128, BK = 16;
    constexpr int WN = BN / 4;        // warp n extent (warps 2x4)
    constexpr int NT = WN / 8;        // n tiles per warp
    constexpr int BF4 = BN * 4 / 256; // float4 loads per thread for B
    __shared__ uint32_t As[2][BM][20];
    __shared__ uint32_t Bs[2][BN][20];

    int z = blockIdx.z;
    long long zh = z >> 3, zl = z & 7;
    A += zh*aHi + zl*aLo;
    B += zh*bHi + zl*bLo;
    C += zh*cHi + zl*cLo;

    int tid = threadIdx.x;
    int warp = tid >> 5, lane = tid & 31;
    int wm = (warp & 1) * 64, wn = (warp >> 1) * WN;
    int g = lane >> 2, tg = lane & 3;
    int bm = blockIdx.y * BM, bn = blockIdx.x * BN;

    float acc[4][NT][4];
    #pragma unroll
    for (int i = 0; i < 4; i++)
        #pragma unroll
        for (int j = 0; j < NT; j++)
            #pragma unroll
            for (int q = 0; q < 4; q++) acc[i][j][q] = 0.f;

    float4 pa[2], pb[BF4];

    auto ldAB = [&](int kt) {
        #pragma unroll
        for (int u = 0; u < 2; u++) {
            int f = tid + u*256, row = f >> 2, k4 = (f & 3) * 4;
            pa[u] = *(const float4*)(A + (size_t)(bm + row)*lda + kt + k4);
        }
        #pragma unroll
        for (int u = 0; u < BF4; u++) {
            int f = tid + u*256;
            if (BT) {
                int row = f >> 2, k4 = (f & 3) * 4;
                pb[u] = *(const float4*)(B + (size_t)(bn + row)*ldb + kt + k4);
            } else {
                int k = f / (BN/4), n4 = (f % (BN/4)) * 4;
                pb[u] = *(const float4*)(B + (size_t)(kt + k)*ldb + bn + n4);
            }
        }
    };
    auto stAB = [&](int buf) {
        #pragma unroll
        for (int u = 0; u < 2; u++) {
            int f = tid + u*256, row = f >> 2, k4 = (f & 3) * 4;
            As[buf][row][k4+0] = f2tf(pa[u].x); As[buf][row][k4+1] = f2tf(pa[u].y);
            As[buf][row][k4+2] = f2tf(pa[u].z); As[buf][row][k4+3] = f2tf(pa[u].w);
        }
        #pragma unroll
        for (int u = 0; u < BF4; u++) {
            int f = tid + u*256;
            if (BT) {
                int row = f >> 2, k4 = (f & 3) * 4;
                Bs[buf][row][k4+0] = f2tf(pb[u].x); Bs[buf][row][k4+1] = f2tf(pb[u].y);
                Bs[buf][row][k4+2] = f2tf(pb[u].z); Bs[buf][row][k4+3] = f2tf(pb[u].w);
            } else {
                int k = f / (BN/4), n4 = (f % (BN/4)) * 4;
                Bs[buf][n4+0][k] = f2tf(pb[u].x); Bs[buf][n4+1][k] = f2tf(pb[u].y);
                Bs[buf][n4+2][k] = f2tf(pb[u].z); Bs[buf][n4+3][k] = f2tf(pb[u].w);
            }
        }
    };

    int nk = K / BK;
    ldAB(0); stAB(0);
    __syncthreads();
    int buf = 0;
    for (int kt = 1; kt <= nk; kt++) {
        if (kt < nk) ldAB(kt * BK);
        #pragma unroll
        for (int ks = 0; ks < 16; ks += 8) {
            uint32_t af[4][4]; uint32_t bf[NT][2];
            #pragma unroll
            for (int i = 0; i < 4; i++) {
                int r = wm + 16*i + g;
                af[i][0] = As[buf][r  ][ks+tg];   af[i][1] = As[buf][r+8][ks+tg];
                af[i][2] = As[buf][r  ][ks+tg+4]; af[i][3] = As[buf][r+8][ks+tg+4];
            }
            #pragma unroll
            for (int j = 0; j < NT; j++) {
                int n = wn + 8*j + g;
                bf[j][0] = Bs[buf][n][ks+tg];
                bf[j][1] = Bs[buf][n][ks+tg+4];
            }
            #pragma unroll
            for (int i = 0; i < 4; i++)
                #pragma unroll
                for (int j = 0; j < NT; j++)
                    mma8(acc[i][j], af[i], bf[j]);
        }
        if (kt < nk) stAB(buf ^ 1);
        __syncthreads();
        buf ^= 1;
    }

    // epilogue
    #pragma unroll
    for (int i = 0; i < 4; i++) {
        int r0 = bm + wm + 16*i + g;
        int r1 = r0 + 8;
        #pragma unroll
        for (int j = 0; j < NT; j++) {
            int c0 = bn + wn + 8*j + tg*2;
            float v00 = acc[i][j][0], v01 = acc[i][j][1];
            float v10 = acc[i][j][2], v11 = acc[i][j][3];
            if (EP == 1 || EP == 2) {
                float b0 = bias[c0], b1 = bias[c0+1];
                v00 += b0; v01 += b1; v10 += b0; v11 += b1;
            }
            if (EP == 1 && addm) {
                v00 += addm[(size_t)r0*ldc + c0]; v01 += addm[(size_t)r0*ldc + c0 + 1];
                v10 += addm[(size_t)r1*ldc + c0]; v11 += addm[(size_t)r1*ldc + c0 + 1];
            }
            if (EP == 2) {
                v00 = 0.5f*v00*(1.0f + erff(v00*0.70710678118654752f));
                v01 = 0.5f*v01*(1.0f + erff(v01*0.70710678118654752f));
                v10 = 0.5f*v10*(1.0f + erff(v10*0.70710678118654752f));
                v11 = 0.5f*v11*(1.0f + erff(v11*0.70710678118654752f));
            }
            if (EP == 3) {
                float rm0 = mask[z*NN + r0] * SCALE, rm1 = mask[z*NN + r1] * SCALE;
                float cm0 = mask[HEADS*NN + z*NN + c0], cm1 = mask[HEADS*NN + z*NN + c0 + 1];
                v00 *= rm0*cm0; v01 *= rm0*cm1; v10 *= rm1*cm0; v11 *= rm1*cm1;
            }
            C[(size_t)r0*ldc + c0]     = v00;
            C[(size_t)r0*ldc + c0 + 1] = v01;
            C[(size_t)r1*ldc + c0]     = v10;
            C[(size_t)r1*ldc + c0 + 1] = v11;
        }
    }
}

// ---------------- launch ----------------
extern "C" void kernel_launch(void* const* d_in, const int* in_sizes, int n_in,
                              void* d_out, int out_size) {
    const float* x      = (const float*)d_in[0];
    const float* ln1_w  = (const float*)d_in[1];
    const float* ln1_b  = (const float*)d_in[2];
    const float* qkv_w  = (const float*)d_in[3];
    const float* out_w  = (const float*)d_in[4];
    const float* out_b  = (const float*)d_in[5];
    const float* conv_w = (const float*)d_in[6];
    const float* conv_b = (const float*)d_in[7];
    const float* ln2_w  = (const float*)d_in[8];
    const float* ln2_b  = (const float*)d_in[9];
    const float* ff1_w  = (const float*)d_in[10];
    const float* ff1_b  = (const float*)d_in[11];
    const float* ff2_w  = (const float*)d_in[12];
    const float* ff2_b  = (const float*)d_in[13];
    float* out = (float*)d_out;

    float *xn, *qkv, *part, *wv, *scores, *mask, *S, *attn, *conv, *xr, *hbuf, *ff;
    cudaGetSymbolAddress((void**)&xn,     g_xn);
    cudaGetSymbolAddress((void**)&qkv,    g_qkv);
    cudaGetSymbolAddress((void**)&part,   g_part);
    cudaGetSymbolAddress((void**)&wv,     g_w);
    cudaGetSymbolAddress((void**)&scores, g_scores);
    cudaGetSymbolAddress((void**)&mask,   g_mask);
    cudaGetSymbolAddress((void**)&S,      g_S);
    cudaGetSymbolAddress((void**)&attn,   g_attn);
    cudaGetSymbolAddress((void**)&conv,   g_conv);
    cudaGetSymbolAddress((void**)&xr,     g_xr);
    cudaGetSymbolAddress((void**)&hbuf,   g_h);
    cudaGetSymbolAddress((void**)&ff,     g_ff);

    // 1. LN1
    ln_kernel<<<M_TOK, 256>>>(x, ln1_w, ln1_b, xn);

    // 2. exact fp32 mask path (independent of tf32 QKV)
    xn_part<<<dim3(8, 8), 512>>>(xn, part);
    wvec<<<HEADS, 512>>>(part, qkv_w, wv);
    head_scores2<<<dim3(HEADS, 128), 256>>>(xn, wv, scores);
    topk_mask<<<2*HEADS, 1024>>>(scores, mask);

    // 3. QKV = xn @ qkv_w^T  (tf32)
    tgemm<128, 0, true><<<dim3(12, 64, 1), 256>>>(
        xn, CC, 0, 0, qkv_w, CC, 0, 0, qkv, 3*CC, 0, 0, CC,
        nullptr, nullptr, nullptr);

    // 4. masked scores S = (q k^T)*scale*rm*cm (tf32, batched over 64 heads)
    tgemm<128, 3, true><<<dim3(8, 8, HEADS), 256>>>(
        qkv,      3*CC, (long long)NN*3*CC, 64,
        qkv + CC, 3*CC, (long long)NN*3*CC, 64,
        S, NN, (long long)8*NN*NN, (long long)NN*NN, 64,
        nullptr, nullptr, mask);

    // 5. softmax
    softmax_rows<<<HEADS*NN, 256>>>(S);

    // 6. P @ V (tf32, batched)
    tgemm<64, 0, false><<<dim3(1, 8, HEADS), 256>>>(
        S, NN, (long long)8*NN*NN, (long long)NN*NN,
        qkv + 2*CC, 3*CC, (long long)NN*3*CC, 64,
        attn, CC, (long long)NN*CC, 64, NN,
        nullptr, nullptr, nullptr);

    // 7. conv branch
    dwconv<<<M_TOK, CC>>>(x, conv_w, conv_b, conv);

    // 8. out-proj + bias + conv -> xr
    tgemm<128, 1, true><<<dim3(4, 64, 1), 256>>>(
        attn, CC, 0, 0, out_w, CC, 0, 0, xr, CC, 0, 0, CC,
        out_b, conv, nullptr);

    // 9. LN2
    ln_kernel<<<M_TOK, 256>>>(xr, ln2_w, ln2_b, hbuf);

    // 10. FF1 + gelu
    tgemm<128, 2, true><<<dim3(16, 64, 1), 256>>>(
        hbuf, CC, 0, 0, ff1_w, CC, 0, 0, ff, FF, 0, 0, CC,
        ff1_b, nullptr, nullptr);

    // 11. FF2 + bias + residual -> out
    tgemm<128, 1, true><<<dim3(4, 64, 1), 256>>>(
        ff, FF, 0, 0, ff2_w, FF, 0, 0, out, CC, 0, 0, FF,
        ff2_b, xr, nullptr);
}

// round 4
// speedup vs baseline: 2.6926x; 1.3495x over previous
#include <cuda_runtime.h>
#include <math.h>
#include <stdint.h>

// ---------------- problem constants ----------------
#define BB 8
#define NN 1024
#define CC 512
#define FF 2048
#define M_TOK (BB*NN)          // 8192
#define HEADS 64
#define SCALE 0.125f           // 64^-0.5

// ---------------- scratch (static device, no allocs) ----------------
__device__ float g_xn[M_TOK*CC];            // ln1 output
__device__ float g_qkv[M_TOK*3*CC];         // qkv
__device__ float g_part[64*CC];             // xn partial sums [b][p][c]
__device__ float g_w[2*HEADS*CC];           // wrow then wcol
__device__ float g_scores[2*HEADS*NN];      // row scores then col scores
__device__ float g_mask[2*HEADS*NN];        // row masks then col masks
__device__ float g_attn[M_TOK*CC];          // attention output (pre-proj)
__device__ float g_conv[M_TOK*CC];          // conv branch
__device__ float g_xr[M_TOK*CC];            // x_attn + x_conv
__device__ float g_h[M_TOK*CC];             // ln2 output
__device__ float g_ff[M_TOK*FF];            // ff1 output

// ---------------- tf32 helpers ----------------
__device__ __forceinline__ uint32_t f2tf(float x) {
    uint32_t u;
    asm("cvt.rna.tf32.f32 %0, %1;" : "=r"(u) : "f"(x));
    return u;
}
__device__ __forceinline__ void mma8(float* c, const uint32_t* a, const uint32_t* b) {
    asm volatile("mma.sync.aligned.m16n8k8.row.col.f32.tf32.tf32.f32 "
                 "{%0,%1,%2,%3},{%4,%5,%6,%7},{%8,%9},{%0,%1,%2,%3};\n"
                 : "+f"(c[0]), "+f"(c[1]), "+f"(c[2]), "+f"(c[3])
                 : "r"(a[0]), "r"(a[1]), "r"(a[2]), "r"(a[3]), "r"(b[0]), "r"(b[1]));
}

// ---------------- layernorm ----------------
__global__ void ln_kernel(const float* __restrict__ x, const float* __restrict__ w,
                          const float* __restrict__ b, float* __restrict__ y) {
    int row = blockIdx.x;
    int tid = threadIdx.x;
    const float* xr = x + (size_t)row*CC;
    float v0 = xr[tid], v1 = xr[tid+256];
    __shared__ float red[256];
    red[tid] = v0 + v1; __syncthreads();
    for (int s = 128; s > 0; s >>= 1) { if (tid < s) red[tid] += red[tid+s]; __syncthreads(); }
    float mu = red[0] * (1.0f/CC);
    __syncthreads();
    float d0 = v0 - mu, d1 = v1 - mu;
    red[tid] = d0*d0 + d1*d1; __syncthreads();
    for (int s = 128; s > 0; s >>= 1) { if (tid < s) red[tid] += red[tid+s]; __syncthreads(); }
    float rs = rsqrtf(red[0] * (1.0f/CC) + 1e-6f);
    float* yr = y + (size_t)row*CC;
    yr[tid]     = d0*rs*w[tid]     + b[tid];
    yr[tid+256] = d1*rs*w[tid+256] + b[tid+256];
}

// ---------------- xn partial sums for per-batch mean ----------------
__global__ void xn_part(const float* __restrict__ xn, float* __restrict__ part) {
    int b = blockIdx.x, p = blockIdx.y;
    int c = threadIdx.x;
    const float* base = xn + ((size_t)b*NN + p*128)*CC + c;
    float s = 0.f;
    #pragma unroll 8
    for (int r = 0; r < 128; r++) s += base[(size_t)r*CC];
    part[(b*8+p)*CC + c] = s;
}

// ---------------- exact-fp32 mask projection vectors ----------------
__global__ void wvec(const float* __restrict__ part, const float* __restrict__ qkv_w,
                     float* __restrict__ w) {
    int bh = blockIdx.x, b = bh >> 3, h = bh & 7;
    int t = threadIdx.x;
    __shared__ float xb[512];
    __shared__ float kb[64], qb[64];
    float s = 0.f;
    #pragma unroll
    for (int p = 0; p < 8; p++) s += part[(b*8+p)*CC + t];
    xb[t] = s * (1.0f/NN);
    __syncthreads();
    if (t < 64) {
        float sq = 0.f, sk = 0.f;
        const float* wq = qkv_w + (size_t)(h*64 + t)*CC;
        const float* wk = qkv_w + (size_t)(CC + h*64 + t)*CC;
        for (int c = 0; c < CC; c++) { sq += wq[c]*xb[c]; sk += wk[c]*xb[c]; }
        qb[t] = sq; kb[t] = sk;
    }
    __syncthreads();
    float wr = 0.f, wc = 0.f;
    #pragma unroll 8
    for (int d = 0; d < 64; d++) {
        wr += qkv_w[(size_t)(h*64+d)*CC + t]    * kb[d];
        wc += qkv_w[(size_t)(CC+h*64+d)*CC + t] * qb[d];
    }
    w[bh*CC + t]            = wr;
    w[HEADS*CC + bh*CC + t] = wc;
}

// ---------------- row/col scores: exact fp32 dot xn . w ----------------
__global__ void head_scores2(const float* __restrict__ xn, const float* __restrict__ w,
                             float* __restrict__ scores) {
    int bh = blockIdx.x, b = bh >> 3;
    int tok0 = blockIdx.y * 8;
    __shared__ float wr[512], wc[512];
    int tid = threadIdx.x;
    wr[tid]     = w[bh*CC + tid];
    wr[tid+256] = w[bh*CC + tid + 256];
    wc[tid]     = w[HEADS*CC + bh*CC + tid];
    wc[tid+256] = w[HEADS*CC + bh*CC + tid + 256];
    __syncthreads();
    int wp = tid >> 5, lane = tid & 31;
    int i = tok0 + wp;
    const float* xr = xn + (size_t)(b*NN + i)*CC;
    float sr = 0.f, sc = 0.f;
    #pragma unroll
    for (int c = lane; c < CC; c += 32) { float v = xr[c]; sr += v*wr[c]; sc += v*wc[c]; }
    #pragma unroll
    for (int o = 16; o > 0; o >>= 1) {
        sr += __shfl_down_sync(~0u, sr, o);
        sc += __shfl_down_sync(~0u, sc, o);
    }
    if (lane == 0) {
        scores[bh*NN + i]            = sr * SCALE;
        scores[HEADS*NN + bh*NN + i] = sc * SCALE;
    }
}

// ---------------- top-k threshold + mask ----------------
__global__ void topk_mask(const float* __restrict__ scores, float* __restrict__ mask) {
    __shared__ float s[1024];
    int blk = blockIdx.x, tid = threadIdx.x;
    float v = scores[(size_t)blk*1024 + tid];
    s[tid] = v; __syncthreads();
    for (int k = 2; k <= 1024; k <<= 1) {
        for (int j = k >> 1; j > 0; j >>= 1) {
            int ixj = tid ^ j;
            if (ixj > tid) {
                bool up = ((tid & k) == 0);
                float a = s[tid], bb = s[ixj];
                if ((a > bb) == up) { s[tid] = bb; s[ixj] = a; }
            }
            __syncthreads();
        }
    }
    float thr = s[512];
    mask[(size_t)blk*1024 + tid] = (v >= thr) ? 1.0f : 0.0f;
}

// ---------------- depthwise 3x3 conv branch ----------------
__global__ void dwconv(const float* __restrict__ x, const float* __restrict__ w,
                       const float* __restrict__ b, float* __restrict__ out) {
    int bn = blockIdx.x;
    int bt = bn >> 10, n = bn & 1023;
    int hh = n >> 5, ww = n & 31;
    int c = threadIdx.x;
    float acc = b[c];
    #pragma unroll
    for (int dh = 0; dh < 3; dh++) {
        int y = hh + dh - 1;
        if (y < 0 || y >= 32) continue;
        #pragma unroll
        for (int dw = 0; dw < 3; dw++) {
            int xw = ww + dw - 1;
            if (xw < 0 || xw >= 32) continue;
            acc += x[(size_t)(bt*NN + y*32 + xw)*CC + c] * w[c*9 + dh*3 + dw];
        }
    }
    out[(size_t)bn*CC + c] = acc;
}

// ---------------- fused flash attention (tf32 mma, online softmax) ----------------
// grid (8 m-blocks, 64 heads), 256 threads. Q tile 128x64, KV tiles 128x64.
// masks folded into operands: Q *= SCALE*rm, K *= cm (exact multiplies).
#define QK_PAD 68
#define P_PAD 132
__global__ void __launch_bounds__(256, 1)
flash_attn(const float* __restrict__ qkv, const float* __restrict__ mask,
           float* __restrict__ out) {
    extern __shared__ uint32_t sm[];
    uint32_t (*Qs)[QK_PAD] = (uint32_t(*)[QK_PAD])sm;
    uint32_t (*Ks)[QK_PAD] = (uint32_t(*)[QK_PAD])(sm + 128*QK_PAD);
    uint32_t (*Vs)[QK_PAD] = (uint32_t(*)[QK_PAD])(sm + 2*128*QK_PAD);
    uint32_t (*Ps)[P_PAD]  = (uint32_t(*)[P_PAD]) (sm + 3*128*QK_PAD);

    int bh = blockIdx.y, b = bh >> 3, h = bh & 7;
    int mb = blockIdx.x * 128;
    int tid = threadIdx.x, warp = tid >> 5, lane = tid & 31;
    int g = lane >> 2, tg = lane & 3;
    int wm = warp * 16;

    const float* qbase = qkv + (size_t)b*NN*(3*CC) + h*64;
    const float* rmask = mask + bh*NN;
    const float* cmask = mask + HEADS*NN + bh*NN;

    // load Q tile, pre-scaled by SCALE*rm
    #pragma unroll
    for (int u = 0; u < 8; u++) {
        int f = tid + u*256;
        int r = f >> 4, c4 = (f & 15) * 4;
        float4 v = *(const float4*)(qbase + (size_t)(mb + r)*(3*CC) + c4);
        float s = SCALE * rmask[mb + r];
        Qs[r][c4+0] = f2tf(v.x*s); Qs[r][c4+1] = f2tf(v.y*s);
        Qs[r][c4+2] = f2tf(v.z*s); Qs[r][c4+3] = f2tf(v.w*s);
    }
    __syncthreads();

    // Q fragments in registers
    uint32_t qf[8][4];
    #pragma unroll
    for (int ks = 0; ks < 8; ks++) {
        qf[ks][0] = Qs[wm+g  ][ks*8+tg];
        qf[ks][1] = Qs[wm+g+8][ks*8+tg];
        qf[ks][2] = Qs[wm+g  ][ks*8+tg+4];
        qf[ks][3] = Qs[wm+g+8][ks*8+tg+4];
    }

    float o[8][4];
    #pragma unroll
    for (int j = 0; j < 8; j++)
        #pragma unroll
        for (int q = 0; q < 4; q++) o[j][q] = 0.f;
    float m0 = -1e30f, m1 = -1e30f, l0 = 0.f, l1 = 0.f;

    for (int kt = 0; kt < 8; kt++) {
        int kv0 = kt * 128;
        __syncthreads();   // previous PV done / Qs frag build done
        // load K (×cm) and V tiles
        #pragma unroll
        for (int u = 0; u < 8; u++) {
            int f = tid + u*256;
            int r = f >> 4, c4 = (f & 15) * 4;
            const float* kp = qbase + CC   + (size_t)(kv0 + r)*(3*CC) + c4;
            const float* vp = qbase + 2*CC + (size_t)(kv0 + r)*(3*CC) + c4;
            float cm = cmask[kv0 + r];
            float4 kv = *(const float4*)kp;
            float4 vv = *(const float4*)vp;
            Ks[r][c4+0] = f2tf(kv.x*cm); Ks[r][c4+1] = f2tf(kv.y*cm);
            Ks[r][c4+2] = f2tf(kv.z*cm); Ks[r][c4+3] = f2tf(kv.w*cm);
            Vs[r][c4+0] = f2tf(vv.x);    Vs[r][c4+1] = f2tf(vv.y);
            Vs[r][c4+2] = f2tf(vv.z);    Vs[r][c4+3] = f2tf(vv.w);
        }
        __syncthreads();

        // S = Q K^T  (per warp: 16 rows x 128 cols)
        float s[16][4];
        #pragma unroll
        for (int j = 0; j < 16; j++)
            #pragma unroll
            for (int q = 0; q < 4; q++) s[j][q] = 0.f;
        #pragma unroll
        for (int j = 0; j < 16; j++) {
            #pragma unroll
            for (int ks = 0; ks < 8; ks++) {
                uint32_t bf[2];
                bf[0] = Ks[j*8+g][ks*8+tg];
                bf[1] = Ks[j*8+g][ks*8+tg+4];
                mma8(s[j], qf[ks], bf);
            }
        }

        // online softmax
        float tm0 = -1e30f, tm1 = -1e30f;
        #pragma unroll
        for (int j = 0; j < 16; j++) {
            tm0 = fmaxf(tm0, fmaxf(s[j][0], s[j][1]));
            tm1 = fmaxf(tm1, fmaxf(s[j][2], s[j][3]));
        }
        tm0 = fmaxf(tm0, __shfl_xor_sync(~0u, tm0, 1));
        tm0 = fmaxf(tm0, __shfl_xor_sync(~0u, tm0, 2));
        tm1 = fmaxf(tm1, __shfl_xor_sync(~0u, tm1, 1));
        tm1 = fmaxf(tm1, __shfl_xor_sync(~0u, tm1, 2));
        float mn0 = fmaxf(m0, tm0), mn1 = fmaxf(m1, tm1);
        float a0 = __expf(m0 - mn0), a1 = __expf(m1 - mn1);
        float rs0 = 0.f, rs1 = 0.f;
        #pragma unroll
        for (int j = 0; j < 16; j++) {
            float p00 = __expf(s[j][0] - mn0);
            float p01 = __expf(s[j][1] - mn0);
            float p10 = __expf(s[j][2] - mn1);
            float p11 = __expf(s[j][3] - mn1);
            rs0 += p00 + p01; rs1 += p10 + p11;
            Ps[wm+g  ][j*8+2*tg]   = f2tf(p00);
            Ps[wm+g  ][j*8+2*tg+1] = f2tf(p01);
            Ps[wm+g+8][j*8+2*tg]   = f2tf(p10);
            Ps[wm+g+8][j*8+2*tg+1] = f2tf(p11);
        }
        rs0 += __shfl_xor_sync(~0u, rs0, 1); rs0 += __shfl_xor_sync(~0u, rs0, 2);
        rs1 += __shfl_xor_sync(~0u, rs1, 1); rs1 += __shfl_xor_sync(~0u, rs1, 2);
        l0 = l0*a0 + rs0; l1 = l1*a1 + rs1;
        m0 = mn0; m1 = mn1;
        #pragma unroll
        for (int j = 0; j < 8; j++) {
            o[j][0] *= a0; o[j][1] *= a0; o[j][2] *= a1; o[j][3] *= a1;
        }
        __syncwarp();

        // O += P @ V
        #pragma unroll
        for (int ks = 0; ks < 16; ks++) {
            uint32_t af[4];
            af[0] = Ps[wm+g  ][ks*8+tg];
            af[1] = Ps[wm+g+8][ks*8+tg];
            af[2] = Ps[wm+g  ][ks*8+tg+4];
            af[3] = Ps[wm+g+8][ks*8+tg+4];
            #pragma unroll
            for (int jd = 0; jd < 8; jd++) {
                uint32_t bf[2];
                bf[0] = Vs[ks*8+tg  ][jd*8+g];
                bf[1] = Vs[ks*8+tg+4][jd*8+g];
                mma8(o[jd], af, bf);
            }
        }
    }

    // epilogue: O /= l
    float il0 = 1.0f / l0, il1 = 1.0f / l1;
    int r0 = b*NN + mb + wm + g, r1 = r0 + 8;
    #pragma unroll
    for (int jd = 0; jd < 8; jd++) {
        int c0 = h*64 + jd*8 + 2*tg;
        out[(size_t)r0*CC + c0]     = o[jd][0]*il0;
        out[(size_t)r0*CC + c0 + 1] = o[jd][1]*il0;
        out[(size_t)r1*CC + c0]     = o[jd][2]*il1;
        out[(size_t)r1*CC + c0 + 1] = o[jd][3]*il1;
    }
}

// ---------------- dense tf32 tensor-core GEMM (NT) ----------------
// C[M,N] = A[M,K] @ B[N,K]^T.  EP: 0 plain; 1 +bias[n](+addm); 2 gelu(v+bias[n]).
template<int EP>
__global__ __launch_bounds__(256)
void tgemm(const float* __restrict__ A, int lda,
           const float* __restrict__ B, int ldb,
           float* __restrict__ C, int ldc, int K,
           const float* __restrict__ bias, const float* __restrict__ addm)
{
    constexpr int BM = 128, BN = 128, BK = 16;
    __shared__ uint32_t As[2][BM][20];
    __shared__ uint32_t Bs[2][BN][20];

    int tid = threadIdx.x;
    int warp = tid >> 5, lane = tid & 31;
    int wm = (warp & 1) * 64, wn = (warp >> 1) * 32;
    int g = lane >> 2, tg = lane & 3;
    int bm = blockIdx.y * BM, bn = blockIdx.x * BN;

    float acc[4][4][4];
    #pragma unroll
    for (int i = 0; i < 4; i++)
        #pragma unroll
        for (int j = 0; j < 4; j++)
            #pragma unroll
            for (int q = 0; q < 4; q++) acc[i][j][q] = 0.f;

    float4 pa[2], pb[2];
    auto ldAB = [&](int kt) {
        #pragma unroll
        for (int u = 0; u < 2; u++) {
            int f = tid + u*256, row = f >> 2, k4 = (f & 3) * 4;
            pa[u] = *(const float4*)(A + (size_t)(bm + row)*lda + kt + k4);
            pb[u] = *(const float4*)(B + (size_t)(bn + row)*ldb + kt + k4);
        }
    };
    auto stAB = [&](int buf) {
        #pragma unroll
        for (int u = 0; u < 2; u++) {
            int f = tid + u*256, row = f >> 2, k4 = (f & 3) * 4;
            As[buf][row][k4+0] = f2tf(pa[u].x); As[buf][row][k4+1] = f2tf(pa[u].y);
            As[buf][row][k4+2] = f2tf(pa[u].z); As[buf][row][k4+3] = f2tf(pa[u].w);
            Bs[buf][row][k4+0] = f2tf(pb[u].x); Bs[buf][row][k4+1] = f2tf(pb[u].y);
            Bs[buf][row][k4+2] = f2tf(pb[u].z); Bs[buf][row][k4+3] = f2tf(pb[u].w);
        }
    };

    int nk = K / BK;
    ldAB(0); stAB(0);
    __syncthreads();
    int buf = 0;
    for (int kt = 1; kt <= nk; kt++) {
        if (kt < nk) ldAB(kt * BK);
        #pragma unroll
        for (int ks = 0; ks < 16; ks += 8) {
            uint32_t af[4][4]; uint32_t bf[4][2];
            #pragma unroll
            for (int i = 0; i < 4; i++) {
                int r = wm + 16*i + g;
                af[i][0] = As[buf][r  ][ks+tg];   af[i][1] = As[buf][r+8][ks+tg];
                af[i][2] = As[buf][r  ][ks+tg+4]; af[i][3] = As[buf][r+8][ks+tg+4];
            }
            #pragma unroll
            for (int j = 0; j < 4; j++) {
                int n = wn + 8*j + g;
                bf[j][0] = Bs[buf][n][ks+tg];
                bf[j][1] = Bs[buf][n][ks+tg+4];
            }
            #pragma unroll
            for (int i = 0; i < 4; i++)
                #pragma unroll
                for (int j = 0; j < 4; j++)
                    mma8(acc[i][j], af[i], bf[j]);
        }
        if (kt < nk) stAB(buf ^ 1);
        __syncthreads();
        buf ^= 1;
    }

    #pragma unroll
    for (int i = 0; i < 4; i++) {
        int r0 = bm + wm + 16*i + g;
        int r1 = r0 + 8;
        #pragma unroll
        for (int j = 0; j < 4; j++) {
            int c0 = bn + wn + 8*j + tg*2;
            float v00 = acc[i][j][0], v01 = acc[i][j][1];
            float v10 = acc[i][j][2], v11 = acc[i][j][3];
            if (EP == 1 || EP == 2) {
                float b0 = bias[c0], b1 = bias[c0+1];
                v00 += b0; v01 += b1; v10 += b0; v11 += b1;
            }
            if (EP == 1 && addm) {
                v00 += addm[(size_t)r0*ldc + c0]; v01 += addm[(size_t)r0*ldc + c0 + 1];
                v10 += addm[(size_t)r1*ldc + c0]; v11 += addm[(size_t)r1*ldc + c0 + 1];
            }
            if (EP == 2) {
                v00 = 0.5f*v00*(1.0f + erff(v00*0.70710678118654752f));
                v01 = 0.5f*v01*(1.0f + erff(v01*0.70710678118654752f));
                v10 = 0.5f*v10*(1.0f + erff(v10*0.70710678118654752f));
                v11 = 0.5f*v11*(1.0f + erff(v11*0.70710678118654752f));
            }
            C[(size_t)r0*ldc + c0]     = v00;
            C[(size_t)r0*ldc + c0 + 1] = v01;
            C[(size_t)r1*ldc + c0]     = v10;
            C[(size_t)r1*ldc + c0 + 1] = v11;
        }
    }
}

// ---------------- launch ----------------
extern "C" void kernel_launch(void* const* d_in, const int* in_sizes, int n_in,
                              void* d_out, int out_size) {
    const float* x      = (const float*)d_in[0];
    const float* ln1_w  = (const float*)d_in[1];
    const float* ln1_b  = (const float*)d_in[2];
    const float* qkv_w  = (const float*)d_in[3];
    const float* out_w  = (const float*)d_in[4];
    const float* out_b  = (const float*)d_in[5];
    const float* conv_w = (const float*)d_in[6];
    const float* conv_b = (const float*)d_in[7];
    const float* ln2_w  = (const float*)d_in[8];
    const float* ln2_b  = (const float*)d_in[9];
    const float* ff1_w  = (const float*)d_in[10];
    const float* ff1_b  = (const float*)d_in[11];
    const float* ff2_w  = (const float*)d_in[12];
    const float* ff2_b  = (const float*)d_in[13];
    float* out = (float*)d_out;

    float *xn, *qkv, *part, *wv, *scores, *mask, *attn, *conv, *xr, *hbuf, *ff;
    cudaGetSymbolAddress((void**)&xn,     g_xn);
    cudaGetSymbolAddress((void**)&qkv,    g_qkv);
    cudaGetSymbolAddress((void**)&part,   g_part);
    cudaGetSymbolAddress((void**)&wv,     g_w);
    cudaGetSymbolAddress((void**)&scores, g_scores);
    cudaGetSymbolAddress((void**)&mask,   g_mask);
    cudaGetSymbolAddress((void**)&attn,   g_attn);
    cudaGetSymbolAddress((void**)&conv,   g_conv);
    cudaGetSymbolAddress((void**)&xr,     g_xr);
    cudaGetSymbolAddress((void**)&hbuf,   g_h);
    cudaGetSymbolAddress((void**)&ff,     g_ff);

    // no static guard: idempotent, called every invocation (capture-safe)
    const int FA_SMEM = (3*128*QK_PAD + 128*P_PAD) * 4;   // 172032 B
    cudaFuncSetAttribute(flash_attn, cudaFuncAttributeMaxDynamicSharedMemorySize, FA_SMEM);

    // 1. LN1
    ln_kernel<<<M_TOK, 256>>>(x, ln1_w, ln1_b, xn);

    // 2. exact fp32 mask path
    xn_part<<<dim3(8, 8), 512>>>(xn, part);
    wvec<<<HEADS, 512>>>(part, qkv_w, wv);
    head_scores2<<<dim3(HEADS, 128), 256>>>(xn, wv, scores);
    topk_mask<<<2*HEADS, 1024>>>(scores, mask);

    // 3. QKV = xn @ qkv_w^T (tf32)
    tgemm<0><<<dim3(12, 64), 256>>>(xn, CC, qkv_w, CC, qkv, 3*CC, CC, nullptr, nullptr);

    // 4. fused attention (QK^T -> mask -> softmax -> PV)
    flash_attn<<<dim3(8, HEADS), 256, FA_SMEM>>>(qkv, mask, attn);

    // 5. conv branch
    dwconv<<<M_TOK, CC>>>(x, conv_w, conv_b, conv);

    // 6. out-proj + bias + conv -> xr
    tgemm<1><<<dim3(4, 64), 256>>>(attn, CC, out_w, CC, xr, CC, CC, out_b, conv);

    // 7. LN2
    ln_kernel<<<M_TOK, 256>>>(xr, ln2_w, ln2_b, hbuf);

    // 8. FF1 + gelu
    tgemm<2><<<dim3(16, 64), 256>>>(hbuf, CC, ff1_w, CC, ff, FF, CC, ff1_b, nullptr);

    // 9. FF2 + bias + residual -> out
    tgemm<1><<<dim3(4, 64), 256>>>(ff, FF, ff2_w, FF, out, CC, FF, ff2_b, xr);
}

// round 7
// speedup vs baseline: 2.9929x; 1.1116x over previous
#include <cuda_runtime.h>
#include <math.h>
#include <stdint.h>

// ---------------- problem constants ----------------
#define BB 8
#define NN 1024
#define CC 512
#define FF 2048
#define M_TOK (BB*NN)          // 8192
#define HEADS 64
#define SCALE 0.125f           // 64^-0.5

// ---------------- scratch (static device, no allocs) ----------------
__device__ float g_xn[M_TOK*CC];            // ln1 output
__device__ float g_qkv[M_TOK*3*CC];         // qkv
__device__ float g_part[64*CC];             // xn partial sums [b][p][c]
__device__ float g_w[2*HEADS*CC];           // wrow then wcol
__device__ float g_scores[2*HEADS*NN];      // row scores then col scores
__device__ float g_mask[2*HEADS*NN];        // row masks then col masks
__device__ float g_attn[M_TOK*CC];          // attention output (pre-proj)
__device__ float g_conv[M_TOK*CC];          // conv branch
__device__ float g_xr[M_TOK*CC];            // x_attn + x_conv
__device__ float g_h[M_TOK*CC];             // ln2 output
__device__ float g_ff[M_TOK*FF];            // ff1 output

// ---------------- helpers ----------------
__device__ __forceinline__ void mma8(float* c, const uint32_t* a, const uint32_t* b) {
    asm volatile("mma.sync.aligned.m16n8k8.row.col.f32.tf32.tf32.f32 "
                 "{%0,%1,%2,%3},{%4,%5,%6,%7},{%8,%9},{%0,%1,%2,%3};\n"
                 : "+f"(c[0]), "+f"(c[1]), "+f"(c[2]), "+f"(c[3])
                 : "r"(a[0]), "r"(a[1]), "r"(a[2]), "r"(a[3]), "r"(b[0]), "r"(b[1]));
}
__device__ __forceinline__ uint32_t smem_u32(const void* p) {
    uint32_t a;
    asm("{ .reg .u64 t; cvta.to.shared.u64 t, %1; cvt.u32.u64 %0, t; }" : "=r"(a) : "l"(p));
    return a;
}
#define CP16(dst, src) \
    asm volatile("cp.async.ca.shared.global [%0], [%1], 16;" :: "r"(dst), "l"(src) : "memory")
#define CP_COMMIT() asm volatile("cp.async.commit_group;" ::: "memory")

// ---------------- layernorm ----------------
__global__ void ln_kernel(const float* __restrict__ x, const float* __restrict__ w,
                          const float* __restrict__ b, float* __restrict__ y) {
    int row = blockIdx.x;
    int tid = threadIdx.x;
    const float* xr = x + (size_t)row*CC;
    float v0 = xr[tid], v1 = xr[tid+256];
    __shared__ float red[256];
    red[tid] = v0 + v1; __syncthreads();
    for (int s = 128; s > 0; s >>= 1) { if (tid < s) red[tid] += red[tid+s]; __syncthreads(); }
    float mu = red[0] * (1.0f/CC);
    __syncthreads();
    float d0 = v0 - mu, d1 = v1 - mu;
    red[tid] = d0*d0 + d1*d1; __syncthreads();
    for (int s = 128; s > 0; s >>= 1) { if (tid < s) red[tid] += red[tid+s]; __syncthreads(); }
    float rs = rsqrtf(red[0] * (1.0f/CC) + 1e-6f);
    float* yr = y + (size_t)row*CC;
    yr[tid]     = d0*rs*w[tid]     + b[tid];
    yr[tid+256] = d1*rs*w[tid+256] + b[tid+256];
}

// ---------------- xn partial sums for per-batch mean ----------------
__global__ void xn_part(const float* __restrict__ xn, float* __restrict__ part) {
    int b = blockIdx.x, p = blockIdx.y;
    int c = threadIdx.x;
    const float* base = xn + ((size_t)b*NN + p*128)*CC + c;
    float s = 0.f;
    #pragma unroll 8
    for (int r = 0; r < 128; r++) s += base[(size_t)r*CC];
    part[(b*8+p)*CC + c] = s;
}

// ---------------- exact-fp32 mask projection vectors ----------------
__global__ void wvec(const float* __restrict__ part, const float* __restrict__ qkv_w,
                     float* __restrict__ w) {
    int bh = blockIdx.x, b = bh >> 3, h = bh & 7;
    int t = threadIdx.x;
    __shared__ float xb[512];
    __shared__ float kb[64], qb[64];
    float s = 0.f;
    #pragma unroll
    for (int p = 0; p < 8; p++) s += part[(b*8+p)*CC + t];
    xb[t] = s * (1.0f/NN);
    __syncthreads();
    if (t < 64) {
        float sq = 0.f, sk = 0.f;
        const float* wq = qkv_w + (size_t)(h*64 + t)*CC;
        const float* wk = qkv_w + (size_t)(CC + h*64 + t)*CC;
        for (int c = 0; c < CC; c++) { sq += wq[c]*xb[c]; sk += wk[c]*xb[c]; }
        qb[t] = sq; kb[t] = sk;
    }
    __syncthreads();
    float wr = 0.f, wc = 0.f;
    #pragma unroll 8
    for (int d = 0; d < 64; d++) {
        wr += qkv_w[(size_t)(h*64+d)*CC + t]    * kb[d];
        wc += qkv_w[(size_t)(CC+h*64+d)*CC + t] * qb[d];
    }
    w[bh*CC + t]            = wr;
    w[HEADS*CC + bh*CC + t] = wc;
}

// ---------------- row/col scores: exact fp32 dot xn . w ----------------
__global__ void head_scores2(const float* __restrict__ xn, const float* __restrict__ w,
                             float* __restrict__ scores) {
    int bh = blockIdx.x, b = bh >> 3;
    int tok0 = blockIdx.y * 8;
    __shared__ float wr[512], wc[512];
    int tid = threadIdx.x;
    wr[tid]     = w[bh*CC + tid];
    wr[tid+256] = w[bh*CC + tid + 256];
    wc[tid]     = w[HEADS*CC + bh*CC + tid];
    wc[tid+256] = w[HEADS*CC + bh*CC + tid + 256];
    __syncthreads();
    int wp = tid >> 5, lane = tid & 31;
    int i = tok0 + wp;
    const float* xr = xn + (size_t)(b*NN + i)*CC;
    float sr = 0.f, sc = 0.f;
    #pragma unroll
    for (int c = lane; c < CC; c += 32) { float v = xr[c]; sr += v*wr[c]; sc += v*wc[c]; }
    #pragma unroll
    for (int o = 16; o > 0; o >>= 1) {
        sr += __shfl_down_sync(~0u, sr, o);
        sc += __shfl_down_sync(~0u, sc, o);
    }
    if (lane == 0) {
        scores[bh*NN + i]            = sr * SCALE;
        scores[HEADS*NN + bh*NN + i] = sc * SCALE;
    }
}

// ---------------- top-k threshold + mask ----------------
__global__ void topk_mask(const float* __restrict__ scores, float* __restrict__ mask) {
    __shared__ float s[1024];
    int blk = blockIdx.x, tid = threadIdx.x;
    float v = scores[(size_t)blk*1024 + tid];
    s[tid] = v; __syncthreads();
    for (int k = 2; k <= 1024; k <<= 1) {
        for (int j = k >> 1; j > 0; j >>= 1) {
            int ixj = tid ^ j;
            if (ixj > tid) {
                bool up = ((tid & k) == 0);
                float a = s[tid], bb = s[ixj];
                if ((a > bb) == up) { s[tid] = bb; s[ixj] = a; }
            }
            __syncthreads();
        }
    }
    float thr = s[512];
    mask[(size_t)blk*1024 + tid] = (v >= thr) ? 1.0f : 0.0f;
}

// ---------------- depthwise 3x3 conv branch ----------------
__global__ void dwconv(const float* __restrict__ x, const float* __restrict__ w,
                       const float* __restrict__ b, float* __restrict__ out) {
    int bn = blockIdx.x;
    int bt = bn >> 10, n = bn & 1023;
    int hh = n >> 5, ww = n & 31;
    int c = threadIdx.x;
    float acc = b[c];
    #pragma unroll
    for (int dh = 0; dh < 3; dh++) {
        int y = hh + dh - 1;
        if (y < 0 || y >= 32) continue;
        #pragma unroll
        for (int dw = 0; dw < 3; dw++) {
            int xw = ww + dw - 1;
            if (xw < 0 || xw >= 32) continue;
            acc += x[(size_t)(bt*NN + y*32 + xw)*CC + c] * w[c*9 + dh*3 + dw];
        }
    }
    out[(size_t)bn*CC + c] = acc;
}

// ---------------- fused flash attention (tf32 mma, online softmax) ----------------
// raw fp32 bits fed to tf32 mma (HW truncates low mantissa bits)
#define QK_PAD 68
#define P_PAD 132
__global__ void __launch_bounds__(256, 1)
flash_attn(const float* __restrict__ qkv, const float* __restrict__ mask,
           float* __restrict__ out) {
    extern __shared__ uint32_t sm[];
    uint32_t (*Qs)[QK_PAD] = (uint32_t(*)[QK_PAD])sm;
    uint32_t (*Ks)[QK_PAD] = (uint32_t(*)[QK_PAD])(sm + 128*QK_PAD);
    uint32_t (*Vs)[QK_PAD] = (uint32_t(*)[QK_PAD])(sm + 2*128*QK_PAD);
    uint32_t (*Ps)[P_PAD]  = (uint32_t(*)[P_PAD]) (sm + 3*128*QK_PAD);

    int bh = blockIdx.y, b = bh >> 3, h = bh & 7;
    int mb = blockIdx.x * 128;
    int tid = threadIdx.x, warp = tid >> 5, lane = tid & 31;
    int g = lane >> 2, tg = lane & 3;
    int wm = warp * 16;

    const float* qbase = qkv + (size_t)b*NN*(3*CC) + h*64;
    const float* rmask = mask + bh*NN;
    const float* cmask = mask + HEADS*NN + bh*NN;

    #pragma unroll
    for (int u = 0; u < 8; u++) {
        int f = tid + u*256;
        int r = f >> 4, c4 = (f & 15) * 4;
        float4 v = *(const float4*)(qbase + (size_t)(mb + r)*(3*CC) + c4);
        float s = SCALE * rmask[mb + r];
        Qs[r][c4+0] = __float_as_uint(v.x*s); Qs[r][c4+1] = __float_as_uint(v.y*s);
        Qs[r][c4+2] = __float_as_uint(v.z*s); Qs[r][c4+3] = __float_as_uint(v.w*s);
    }
    __syncthreads();

    uint32_t qf[8][4];
    #pragma unroll
    for (int ks = 0; ks < 8; ks++) {
        qf[ks][0] = Qs[wm+g  ][ks*8+tg];
        qf[ks][1] = Qs[wm+g+8][ks*8+tg];
        qf[ks][2] = Qs[wm+g  ][ks*8+tg+4];
        qf[ks][3] = Qs[wm+g+8][ks*8+tg+4];
    }

    float o[8][4];
    #pragma unroll
    for (int j = 0; j < 8; j++)
        #pragma unroll
        for (int q = 0; q < 4; q++) o[j][q] = 0.f;
    float m0 = -1e30f, m1 = -1e30f, l0 = 0.f, l1 = 0.f;

    for (int kt = 0; kt < 8; kt++) {
        int kv0 = kt * 128;
        __syncthreads();
        #pragma unroll
        for (int u = 0; u < 8; u++) {
            int f = tid + u*256;
            int r = f >> 4, c4 = (f & 15) * 4;
            const float* kp = qbase + CC   + (size_t)(kv0 + r)*(3*CC) + c4;
            const float* vp = qbase + 2*CC + (size_t)(kv0 + r)*(3*CC) + c4;
            float cm = cmask[kv0 + r];
            float4 kv = *(const float4*)kp;
            float4 vv = *(const float4*)vp;
            Ks[r][c4+0] = __float_as_uint(kv.x*cm); Ks[r][c4+1] = __float_as_uint(kv.y*cm);
            Ks[r][c4+2] = __float_as_uint(kv.z*cm); Ks[r][c4+3] = __float_as_uint(kv.w*cm);
            Vs[r][c4+0] = __float_as_uint(vv.x);    Vs[r][c4+1] = __float_as_uint(vv.y);
            Vs[r][c4+2] = __float_as_uint(vv.z);    Vs[r][c4+3] = __float_as_uint(vv.w);
        }
        __syncthreads();

        float s[16][4];
        #pragma unroll
        for (int j = 0; j < 16; j++)
            #pragma unroll
            for (int q = 0; q < 4; q++) s[j][q] = 0.f;
        #pragma unroll
        for (int j = 0; j < 16; j++) {
            #pragma unroll
            for (int ks = 0; ks < 8; ks++) {
                uint32_t bf[2];
                bf[0] = Ks[j*8+g][ks*8+tg];
                bf[1] = Ks[j*8+g][ks*8+tg+4];
                mma8(s[j], qf[ks], bf);
            }
        }

        float tm0 = -1e30f, tm1 = -1e30f;
        #pragma unroll
        for (int j = 0; j < 16; j++) {
            tm0 = fmaxf(tm0, fmaxf(s[j][0], s[j][1]));
            tm1 = fmaxf(tm1, fmaxf(s[j][2], s[j][3]));
        }
        tm0 = fmaxf(tm0, __shfl_xor_sync(~0u, tm0, 1));
        tm0 = fmaxf(tm0, __shfl_xor_sync(~0u, tm0, 2));
        tm1 = fmaxf(tm1, __shfl_xor_sync(~0u, tm1, 1));
        tm1 = fmaxf(tm1, __shfl_xor_sync(~0u, tm1, 2));
        float mn0 = fmaxf(m0, tm0), mn1 = fmaxf(m1, tm1);
        float a0 = __expf(m0 - mn0), a1 = __expf(m1 - mn1);
        float rs0 = 0.f, rs1 = 0.f;
        #pragma unroll
        for (int j = 0; j < 16; j++) {
            float p00 = __expf(s[j][0] - mn0);
            float p01 = __expf(s[j][1] - mn0);
            float p10 = __expf(s[j][2] - mn1);
            float p11 = __expf(s[j][3] - mn1);
            rs0 += p00 + p01; rs1 += p10 + p11;
            Ps[wm+g  ][j*8+2*tg]   = __float_as_uint(p00);
            Ps[wm+g  ][j*8+2*tg+1] = __float_as_uint(p01);
            Ps[wm+g+8][j*8+2*tg]   = __float_as_uint(p10);
            Ps[wm+g+8][j*8+2*tg+1] = __float_as_uint(p11);
        }
        rs0 += __shfl_xor_sync(~0u, rs0, 1); rs0 += __shfl_xor_sync(~0u, rs0, 2);
        rs1 += __shfl_xor_sync(~0u, rs1, 1); rs1 += __shfl_xor_sync(~0u, rs1, 2);
        l0 = l0*a0 + rs0; l1 = l1*a1 + rs1;
        m0 = mn0; m1 = mn1;
        #pragma unroll
        for (int j = 0; j < 8; j++) {
            o[j][0] *= a0; o[j][1] *= a0; o[j][2] *= a1; o[j][3] *= a1;
        }
        __syncwarp();

        #pragma unroll
        for (int ks = 0; ks < 16; ks++) {
            uint32_t af[4];
            af[0] = Ps[wm+g  ][ks*8+tg];
            af[1] = Ps[wm+g+8][ks*8+tg];
            af[2] = Ps[wm+g  ][ks*8+tg+4];
            af[3] = Ps[wm+g+8][ks*8+tg+4];
            #pragma unroll
            for (int jd = 0; jd < 8; jd++) {
                uint32_t bf[2];
                bf[0] = Vs[ks*8+tg  ][jd*8+g];
                bf[1] = Vs[ks*8+tg+4][jd*8+g];
                mma8(o[jd], af, bf);
            }
        }
    }

    float il0 = 1.0f / l0, il1 = 1.0f / l1;
    int r0 = b*NN + mb + wm + g, r1 = r0 + 8;
    #pragma unroll
    for (int jd = 0; jd < 8; jd++) {
        int c0 = h*64 + jd*8 + 2*tg;
        out[(size_t)r0*CC + c0]     = o[jd][0]*il0;
        out[(size_t)r0*CC + c0 + 1] = o[jd][1]*il0;
        out[(size_t)r1*CC + c0]     = o[jd][2]*il1;
        out[(size_t)r1*CC + c0 + 1] = o[jd][3]*il1;
    }
}

// ---------------- tf32 tensor-core GEMM (NT), cp.async 3-stage pipeline ----------
// C[M,N] = A[M,K] @ B[N,K]^T. raw fp32 in dynamic smem, HW truncates to tf32.
// EP: 0 plain; 1 +bias[n](+addm); 2 gelu(v+bias[n]).
// dynamic smem: 3 stages x (A 128x20 + B 128x20) floats = 61440 B
#define TG_STG 3
#define TG_STRIDE 20
#define TG_STAGE_F (128 * TG_STRIDE)              // floats per operand stage
#define TG_SMEM (TG_STG * 2 * TG_STAGE_F * 4)     // 61440 bytes
template<int EP>
__global__ __launch_bounds__(256)
void tgemm(const float* __restrict__ A, int lda,
           const float* __restrict__ B, int ldb,
           float* __restrict__ C, int ldc, int K,
           const float* __restrict__ bias, const float* __restrict__ addm)
{
    constexpr int BM = 128, BN = 128, BK = 16;
    extern __shared__ float tsm[];
    // layout: [stage][A(2560) then B(2560)]
    auto As = [&](int s) -> float* { return tsm + s * 2 * TG_STAGE_F; };
    auto Bs = [&](int s) -> float* { return tsm + s * 2 * TG_STAGE_F + TG_STAGE_F; };

    int tid = threadIdx.x;
    int warp = tid >> 5, lane = tid & 31;
    int wm = (warp & 1) * 64, wn = (warp >> 1) * 32;
    int g = lane >> 2, tg = lane & 3;
    int bm = blockIdx.y * BM, bn = blockIdx.x * BN;

    float acc[4][4][4];
    #pragma unroll
    for (int i = 0; i < 4; i++)
        #pragma unroll
        for (int j = 0; j < 4; j++)
            #pragma unroll
            for (int q = 0; q < 4; q++) acc[i][j][q] = 0.f;

    int lrow = tid >> 2, lk4 = (tid & 3) * 4;
    const float* Ab = A + (size_t)(bm + lrow) * lda + lk4;
    const float* Bb = B + (size_t)(bn + lrow) * ldb + lk4;
    const float* Ab2 = Ab + (size_t)64 * lda;     // rows 64..127
    const float* Bb2 = Bb + (size_t)64 * ldb;

    auto issue = [&](int kt, int s) {
        CP16(smem_u32(As(s) + lrow*TG_STRIDE + lk4),        Ab  + kt);
        CP16(smem_u32(As(s) + (lrow+64)*TG_STRIDE + lk4),   Ab2 + kt);
        CP16(smem_u32(Bs(s) + lrow*TG_STRIDE + lk4),        Bb  + kt);
        CP16(smem_u32(Bs(s) + (lrow+64)*TG_STRIDE + lk4),   Bb2 + kt);
        CP_COMMIT();
    };

    int nk = K / BK;
    issue(0, 0);
    if (nk > 1) issue(BK, 1);

    for (int c = 0; c < nk; c++) {
        if (c + 1 < nk) asm volatile("cp.async.wait_group 1;" ::: "memory");
        else            asm volatile("cp.async.wait_group 0;" ::: "memory");
        __syncthreads();
        int s = c % TG_STG;
        const float* as = As(s);
        const float* bs = Bs(s);

        #pragma unroll
        for (int ks = 0; ks < 16; ks += 8) {
            uint32_t af[4][4]; uint32_t bf[4][2];
            #pragma unroll
            for (int i = 0; i < 4; i++) {
                int r = wm + 16*i + g;
                af[i][0] = __float_as_uint(as[r*TG_STRIDE     + ks+tg]);
                af[i][1] = __float_as_uint(as[(r+8)*TG_STRIDE + ks+tg]);
                af[i][2] = __float_as_uint(as[r*TG_STRIDE     + ks+tg+4]);
                af[i][3] = __float_as_uint(as[(r+8)*TG_STRIDE + ks+tg+4]);
            }
            #pragma unroll
            for (int j = 0; j < 4; j++) {
                int n = wn + 8*j + g;
                bf[j][0] = __float_as_uint(bs[n*TG_STRIDE + ks+tg]);
                bf[j][1] = __float_as_uint(bs[n*TG_STRIDE + ks+tg+4]);
            }
            #pragma unroll
            for (int i = 0; i < 4; i++)
                #pragma unroll
                for (int j = 0; j < 4; j++)
                    mma8(acc[i][j], af[i], bf[j]);
        }

        if (c + 2 < nk) issue((c + 2) * BK, (c + 2) % TG_STG);
    }

    #pragma unroll
    for (int i = 0; i < 4; i++) {
        int r0 = bm + wm + 16*i + g;
        int r1 = r0 + 8;
        #pragma unroll
        for (int j = 0; j < 4; j++) {
            int c0 = bn + wn + 8*j + tg*2;
            float v00 = acc[i][j][0], v01 = acc[i][j][1];
            float v10 = acc[i][j][2], v11 = acc[i][j][3];
            if (EP == 1 || EP == 2) {
                float b0 = bias[c0], b1 = bias[c0+1];
                v00 += b0; v01 += b1; v10 += b0; v11 += b1;
            }
            if (EP == 1 && addm) {
                v00 += addm[(size_t)r0*ldc + c0]; v01 += addm[(size_t)r0*ldc + c0 + 1];
                v10 += addm[(size_t)r1*ldc + c0]; v11 += addm[(size_t)r1*ldc + c0 + 1];
            }
            if (EP == 2) {
                v00 = 0.5f*v00*(1.0f + erff(v00*0.70710678118654752f));
                v01 = 0.5f*v01*(1.0f + erff(v01*0.70710678118654752f));
                v10 = 0.5f*v10*(1.0f + erff(v10*0.70710678118654752f));
                v11 = 0.5f*v11*(1.0f + erff(v11*0.70710678118654752f));
            }
            C[(size_t)r0*ldc + c0]     = v00;
            C[(size_t)r0*ldc + c0 + 1] = v01;
            C[(size_t)r1*ldc + c0]     = v10;
            C[(size_t)r1*ldc + c0 + 1] = v11;
        }
    }
}

// ---------------- launch ----------------
extern "C" void kernel_launch(void* const* d_in, const int* in_sizes, int n_in,
                              void* d_out, int out_size) {
    const float* x      = (const float*)d_in[0];
    const float* ln1_w  = (const float*)d_in[1];
    const float* ln1_b  = (const float*)d_in[2];
    const float* qkv_w  = (const float*)d_in[3];
    const float* out_w  = (const float*)d_in[4];
    const float* out_b  = (const float*)d_in[5];
    const float* conv_w = (const float*)d_in[6];
    const float* conv_b = (const float*)d_in[7];
    const float* ln2_w  = (const float*)d_in[8];
    const float* ln2_b  = (const float*)d_in[9];
    const float* ff1_w  = (const float*)d_in[10];
    const float* ff1_b  = (const float*)d_in[11];
    const float* ff2_w  = (const float*)d_in[12];
    const float* ff2_b  = (const float*)d_in[13];
    float* out = (float*)d_out;

    float *xn, *qkv, *part, *wv, *scores, *mask, *attn, *conv, *xr, *hbuf, *ff;
    cudaGetSymbolAddress((void**)&xn,     g_xn);
    cudaGetSymbolAddress((void**)&qkv,    g_qkv);
    cudaGetSymbolAddress((void**)&part,   g_part);
    cudaGetSymbolAddress((void**)&wv,     g_w);
    cudaGetSymbolAddress((void**)&scores, g_scores);
    cudaGetSymbolAddress((void**)&mask,   g_mask);
    cudaGetSymbolAddress((void**)&attn,   g_attn);
    cudaGetSymbolAddress((void**)&conv,   g_conv);
    cudaGetSymbolAddress((void**)&xr,     g_xr);
    cudaGetSymbolAddress((void**)&hbuf,   g_h);
    cudaGetSymbolAddress((void**)&ff,     g_ff);

    // idempotent every call (capture-safe, no static guards)
    const int FA_SMEM = (3*128*QK_PAD + 128*P_PAD) * 4;   // 172032 B
    cudaFuncSetAttribute(flash_attn, cudaFuncAttributeMaxDynamicSharedMemorySize, FA_SMEM);
    cudaFuncSetAttribute(tgemm<0>, cudaFuncAttributeMaxDynamicSharedMemorySize, TG_SMEM);
    cudaFuncSetAttribute(tgemm<1>, cudaFuncAttributeMaxDynamicSharedMemorySize, TG_SMEM);
    cudaFuncSetAttribute(tgemm<2>, cudaFuncAttributeMaxDynamicSharedMemorySize, TG_SMEM);

    // 1. LN1
    ln_kernel<<<M_TOK, 256>>>(x, ln1_w, ln1_b, xn);

    // 2. exact fp32 mask path
    xn_part<<<dim3(8, 8), 512>>>(xn, part);
    wvec<<<HEADS, 512>>>(part, qkv_w, wv);
    head_scores2<<<dim3(HEADS, 128), 256>>>(xn, wv, scores);
    topk_mask<<<2*HEADS, 1024>>>(scores, mask);

    // 3. QKV = xn @ qkv_w^T (tf32, cp.async pipeline)
    tgemm<0><<<dim3(12, 64), 256, TG_SMEM>>>(xn, CC, qkv_w, CC, qkv, 3*CC, CC, nullptr, nullptr);

    // 4. fused attention
    flash_attn<<<dim3(8, HEADS), 256, FA_SMEM>>>(qkv, mask, attn);

    // 5. conv branch
    dwconv<<<M_TOK, CC>>>(x, conv_w, conv_b, conv);

    // 6. out-proj + bias + conv -> xr
    tgemm<1><<<dim3(4, 64), 256, TG_SMEM>>>(attn, CC, out_w, CC, xr, CC, CC, out_b, conv);

    // 7. LN2
    ln_kernel<<<M_TOK, 256>>>(xr, ln2_w, ln2_b, hbuf);

    // 8. FF1 + gelu
    tgemm<2><<<dim3(16, 64), 256, TG_SMEM>>>(hbuf, CC, ff1_w, CC, ff, FF, CC, ff1_b, nullptr);

    // 9. FF2 + bias + residual -> out
    tgemm<1><<<dim3(4, 64), 256, TG_SMEM>>>(ff, FF, ff2_w, FF, out, CC, FF, ff2_b, xr);
}